// round 8
// baseline (speedup 1.0000x reference)
#include <cuda_runtime.h>
#include <cuda_bf16.h>

// RoIAlign1D: feat [B,T,D] f32, spans [B,K,2] i32, lengths [B] i32 -> out [B,K,P,D] f32
// P = 16, D = 512 (128 float4).
//
// R8: one block per (RoI, 4 samples), grid = B*K*4 = 4096, 128 threads.
// Software-pipelined loads: 2 samples (4 LDG.128) issued up front (MLP_p1=4,
// same burst as R6 to avoid cross-CTA L1tex queue spread), then each next
// sample's loads issue before the current sample is consumed -> ~6 loads
// sustained in flight (R4-level latency hiding). 3 rotating float4-pair
// buffers keep live data regs at 24. __launch_bounds__(128,13) = 39-reg
// budget / 52-warp cap, also stops ptxas from re-front-batching the loads.

#define P_SAMPLES 16
#define PG 4   // samples per block

__global__ void __launch_bounds__(128, 13) roialign1d_kernel(
    const float4* __restrict__ feat,   // [B, T, 128]
    const int*    __restrict__ spans,  // [B, K, 2]
    const int*    __restrict__ lengths,// [B]
    float4*       __restrict__ out,    // [B, K, P, 128]
    int K, int T, int D4)
{
    const int blk = blockIdx.x;                  // bk*4 + pg
    const int pg  = blk & 3;
    const int bk  = blk >> 2;                    // b*K + k
    const int b   = bk / K;
    const int tid = threadIdx.x;                 // d4 lane, 0..127

    // ---- span math, once per block (uniform) ----
    const int Lm1 = __ldg(&lengths[b]) - 1;
    int a0 = __ldg(&spans[bk * 2 + 0]);
    int a1 = __ldg(&spans[bk * 2 + 1]);
    a0 = min(max(a0, 0), Lm1);
    a1 = min(max(a1, 0), Lm1);
    const int s     = min(a0, a1);
    const int segm1 = max(a0, a1) - s;           // seglen - 1
    const float segf = (float)segm1;

    const int fbase = (b * T + s) * D4 + tid;
    const int obase = (bk * P_SAMPLES + pg * PG) * D4 + tid;

    // per-sample indices/weights (uniform scalars)
    int   o0[PG], o1[PG];
    float w[PG];
    #pragma unroll
    for (int u = 0; u < PG; u++) {
        const int pp = pg * PG + u;
        const float t   = (float)pp / (float)(P_SAMPLES - 1);  // const-folded
        const float idx = t * segf;
        int i0 = (int)floorf(idx);
        i0 = min(i0, segm1);
        const int i1 = min(i0 + 1, segm1);
        w[u]  = idx - (float)i0;
        o0[u] = fbase + i0 * D4;
        o1[u] = fbase + i1 * D4;
    }

    // ---- depth-2 software pipeline over 3 rotating buffers ----
    float4 A0, A1, B0, B1, C0, C1;

    // prologue: samples 0 and 1 in flight (MLP_p1 = 4)
    A0 = feat[o0[0]]; A1 = feat[o1[0]];
    B0 = feat[o0[1]]; B1 = feat[o1[1]];

    // u=0: issue sample 2, consume sample 0
    C0 = feat[o0[2]]; C1 = feat[o1[2]];
    {
        float4 r;
        r.x = fmaf(w[0], A1.x - A0.x, A0.x);
        r.y = fmaf(w[0], A1.y - A0.y, A0.y);
        r.z = fmaf(w[0], A1.z - A0.z, A0.z);
        r.w = fmaf(w[0], A1.w - A0.w, A0.w);
        __stcs(&out[obase + 0 * D4], r);
    }

    // u=1: issue sample 3 (reuse A), consume sample 1
    A0 = feat[o0[3]]; A1 = feat[o1[3]];
    {
        float4 r;
        r.x = fmaf(w[1], B1.x - B0.x, B0.x);
        r.y = fmaf(w[1], B1.y - B0.y, B0.y);
        r.z = fmaf(w[1], B1.z - B0.z, B0.z);
        r.w = fmaf(w[1], B1.w - B0.w, B0.w);
        __stcs(&out[obase + 1 * D4], r);
    }

    // u=2: consume sample 2
    {
        float4 r;
        r.x = fmaf(w[2], C1.x - C0.x, C0.x);
        r.y = fmaf(w[2], C1.y - C0.y, C0.y);
        r.z = fmaf(w[2], C1.z - C0.z, C0.z);
        r.w = fmaf(w[2], C1.w - C0.w, C0.w);
        __stcs(&out[obase + 2 * D4], r);
    }

    // u=3: consume sample 3
    {
        float4 r;
        r.x = fmaf(w[3], A1.x - A0.x, A0.x);
        r.y = fmaf(w[3], A1.y - A0.y, A0.y);
        r.z = fmaf(w[3], A1.z - A0.z, A0.z);
        r.w = fmaf(w[3], A1.w - A0.w, A0.w);
        __stcs(&out[obase + 3 * D4], r);
    }
}

extern "C" void kernel_launch(void* const* d_in, const int* in_sizes, int n_in,
                              void* d_out, int out_size)
{
    const float* feat    = (const float*)d_in[0];
    const int*   spans   = (const int*)d_in[1];
    const int*   lengths = (const int*)d_in[2];
    float*       out     = (float*)d_out;

    const int B  = in_sizes[2];                      // 16
    const int K  = in_sizes[1] / (2 * B);            // 64
    const int TD = in_sizes[0] / B;                  // T*D
    const int D  = out_size / (B * K * P_SAMPLES);   // 512
    const int T  = TD / D;                           // 4096
    const int D4 = D / 4;                            // 128

    const int nblocks = B * K * (P_SAMPLES / PG);    // 4096
    roialign1d_kernel<<<nblocks, D4>>>(
        (const float4*)feat, spans, lengths, (float4*)out, K, T, D4);
}

// round 9
// speedup vs baseline: 1.1195x; 1.1195x over previous
#include <cuda_runtime.h>
#include <cuda_bf16.h>

// RoIAlign1D: feat [B,T,D] f32, spans [B,K,2] i32, lengths [B] i32 -> out [B,K,P,D] f32
// P = 16, D = 512 (128 float4).
//
// R9 = R6 (best: 10.7us) minus __stcs. Working set feat(~64MB touched) +
// out(32MB) = ~96MB < 126MB L2, so default write-back stores let `out` stay
// resident dirty in L2 across graph replays -> steady-state DRAM write
// traffic collapses (was 30MB/replay forced out by the evict-first hint).
// Everything else identical: grid B*K*8, 128 thr, MLP_p1=4, 64-warp occ cap.

#define P_SAMPLES 16
#define PG 2   // samples per block

__global__ void __launch_bounds__(128, 16) roialign1d_kernel(
    const float4* __restrict__ feat,   // [B, T, 128]
    const int*    __restrict__ spans,  // [B, K, 2]
    const int*    __restrict__ lengths,// [B]
    float4*       __restrict__ out,    // [B, K, P, 128]
    int K, int T, int D4)
{
    const int blk = blockIdx.x;                  // bk*8 + pg
    const int pg  = blk & 7;
    const int bk  = blk >> 3;                    // b*K + k
    const int b   = bk / K;
    const int tid = threadIdx.x;                 // d4 lane, 0..127

    // ---- span math, once per block (uniform) ----
    const int Lm1 = __ldg(&lengths[b]) - 1;
    int a0 = __ldg(&spans[bk * 2 + 0]);
    int a1 = __ldg(&spans[bk * 2 + 1]);
    a0 = min(max(a0, 0), Lm1);
    a1 = min(max(a1, 0), Lm1);
    const int s     = min(a0, a1);
    const int segm1 = max(a0, a1) - s;           // seglen - 1
    const float segf = (float)segm1;

    const int fbase = (b * T + s) * D4 + tid;
    const int obase = (bk * P_SAMPLES + pg * PG) * D4 + tid;

    float4 f0[PG], f1[PG];
    float  w[PG];
    #pragma unroll
    for (int u = 0; u < PG; u++) {
        const int pp = pg * PG + u;
        const float t   = (float)pp / (float)(P_SAMPLES - 1);
        const float idx = t * segf;
        int i0 = (int)floorf(idx);
        i0 = min(i0, segm1);
        const int i1 = min(i0 + 1, segm1);
        w[u] = idx - (float)i0;
        f0[u] = feat[fbase + i0 * D4];
        f1[u] = feat[fbase + i1 * D4];
    }
    #pragma unroll
    for (int u = 0; u < PG; u++) {
        float4 r;
        r.x = fmaf(w[u], f1[u].x - f0[u].x, f0[u].x);
        r.y = fmaf(w[u], f1[u].y - f0[u].y, f0[u].y);
        r.z = fmaf(w[u], f1[u].z - f0[u].z, f0[u].z);
        r.w = fmaf(w[u], f1[u].w - f0[u].w, f0[u].w);
        out[obase + u * D4] = r;                 // default write-back: stay in L2
    }
}

extern "C" void kernel_launch(void* const* d_in, const int* in_sizes, int n_in,
                              void* d_out, int out_size)
{
    const float* feat    = (const float*)d_in[0];
    const int*   spans   = (const int*)d_in[1];
    const int*   lengths = (const int*)d_in[2];
    float*       out     = (float*)d_out;

    const int B  = in_sizes[2];                      // 16
    const int K  = in_sizes[1] / (2 * B);            // 64
    const int TD = in_sizes[0] / B;                  // T*D
    const int D  = out_size / (B * K * P_SAMPLES);   // 512
    const int T  = TD / D;                           // 4096
    const int D4 = D / 4;                            // 128

    const int nblocks = B * K * (P_SAMPLES / PG);    // 8192
    roialign1d_kernel<<<nblocks, D4>>>(
        (const float4*)feat, spans, lengths, (float4*)out, K, T, D4);
}